// round 1
// baseline (speedup 1.0000x reference)
#include <cuda_runtime.h>
#include <cuda_bf16.h>

#define NG 128
#define NPMAX 200000
#define NRMAX 400000

// ---- static scratch (no allocations allowed) ----
__device__ __align__(16) float g_p_xw [NPMAX * 64];
__device__ __align__(16) float g_r_xw [NRMAX * 64];
__device__ __align__(16) float g_p_acc[NPMAX * 64];
__device__ __align__(16) float g_r_acc[NRMAX * 64];
__device__ float g_p_dinv[NPMAX];
__device__ float g_r_dinv[NRMAX];
__device__ float g_pool[NG * 128];   // [g][0..63] = p-branch sums, [64..127] = r-branch sums
__device__ float g_cnt[2 * NG];      // node counts per graph: [0..127]=p, [128..255]=r

// ---------------------------------------------------------------------------
// init: deg = 1 (self loop), pool/cnt = 0
// ---------------------------------------------------------------------------
__global__ void k_init(int np, int nr) {
    int i = blockIdx.x * blockDim.x + threadIdx.x;
    if (i < np) g_p_dinv[i] = 1.0f;
    if (i < nr) g_r_dinv[i] = 1.0f;
    if (i < NG * 128) g_pool[i] = 0.0f;
    if (i < 2 * NG) g_cnt[i] = 0.0f;
}

// deg[dst] += 1 over edges
__global__ void k_count(const int* __restrict__ dst, int E, float* __restrict__ deg) {
    int e = blockIdx.x * blockDim.x + threadIdx.x;
    if (e < E) atomicAdd(&deg[dst[e]], 1.0f);
}

// dinv = rsqrt(deg)   (deg >= 1 always due to self loop)
__global__ void k_dinv(float* __restrict__ d, int n) {
    int i = blockIdx.x * blockDim.x + threadIdx.x;
    if (i < n) d[i] = rsqrtf(d[i]);
}

// ---------------------------------------------------------------------------
// GEMM: XW[M,64] = X[M,K] @ W[K,64], fp32 SIMT, 64x64 block tile, 256 threads,
// 4x4 per-thread microtile, K chunks of 8. Requires M%64==0, K%8==0 (holds:
// M in {200000,400000}, K in {1280,120}).
// ---------------------------------------------------------------------------
#define KC 8
__global__ __launch_bounds__(256) void k_gemm(const float* __restrict__ X,
                                              const float* __restrict__ W,
                                              float* __restrict__ XW,
                                              int M, int K) {
    __shared__ __align__(16) float As[KC][64];   // transposed A tile: As[k][m]
    __shared__ __align__(16) float Bs[KC][64];   // Bs[k][n]
    int t  = threadIdx.x;
    int tx = t & 15;          // col group 0..15
    int ty = t >> 4;          // row group 0..15
    int m0 = blockIdx.x * 64;

    // loader mapping
    int la_row = t >> 2;            // 0..63
    int la_k   = (t & 3) * 2;       // 0,2,4,6
    int lb_k   = t >> 5;            // 0..7
    int lb_f   = (t & 31) * 2;      // 0..62

    float acc[4][4];
#pragma unroll
    for (int i = 0; i < 4; i++)
#pragma unroll
        for (int j = 0; j < 4; j++) acc[i][j] = 0.0f;

    for (int k0 = 0; k0 < K; k0 += KC) {
        float2 av = *(const float2*)(X + (size_t)(m0 + la_row) * K + k0 + la_k);
        As[la_k][la_row]     = av.x;
        As[la_k + 1][la_row] = av.y;
        float2 bv = *(const float2*)(W + (size_t)(k0 + lb_k) * 64 + lb_f);
        Bs[lb_k][lb_f]     = bv.x;
        Bs[lb_k][lb_f + 1] = bv.y;
        __syncthreads();
#pragma unroll
        for (int kk = 0; kk < KC; kk++) {
            float4 a = *(const float4*)&As[kk][ty * 4];
            float4 b = *(const float4*)&Bs[kk][tx * 4];
            acc[0][0] += a.x * b.x; acc[0][1] += a.x * b.y; acc[0][2] += a.x * b.z; acc[0][3] += a.x * b.w;
            acc[1][0] += a.y * b.x; acc[1][1] += a.y * b.y; acc[1][2] += a.y * b.z; acc[1][3] += a.y * b.w;
            acc[2][0] += a.z * b.x; acc[2][1] += a.z * b.y; acc[2][2] += a.z * b.z; acc[2][3] += a.z * b.w;
            acc[3][0] += a.w * b.x; acc[3][1] += a.w * b.y; acc[3][2] += a.w * b.z; acc[3][3] += a.w * b.w;
        }
        __syncthreads();
    }
#pragma unroll
    for (int i = 0; i < 4; i++) {
        float4 v = make_float4(acc[i][0], acc[i][1], acc[i][2], acc[i][3]);
        *(float4*)(XW + (size_t)(m0 + ty * 4 + i) * 64 + tx * 4) = v;
    }
}

// ---------------------------------------------------------------------------
// acc[i] = xw[i] * dinv[i]^2   (self-loop contribution; also zero-init of acc)
// one thread per float4 (n*16 threads)
// ---------------------------------------------------------------------------
__global__ void k_selfloop(const float* __restrict__ xw, const float* __restrict__ dinv,
                           float* __restrict__ acc, int n) {
    int i = blockIdx.x * blockDim.x + threadIdx.x;
    if (i < n * 16) {
        int node = i >> 4;
        float s = dinv[node];
        s = s * s;
        float4 v = ((const float4*)xw)[i];
        v.x *= s; v.y *= s; v.z *= s; v.w *= s;
        ((float4*)acc)[i] = v;
    }
}

// ---------------------------------------------------------------------------
// edge scatter: acc[dst] += dinv[src]*dinv[dst] * xw[src]
// 16 threads per edge, 4 floats each (float4 gather, scalar RED.ADD)
// ---------------------------------------------------------------------------
__global__ void k_scatter(const int* __restrict__ src, const int* __restrict__ dst,
                          const float* __restrict__ dinv, const float* __restrict__ xw,
                          float* __restrict__ acc, int E) {
    int t = blockIdx.x * blockDim.x + threadIdx.x;
    int e = t >> 4;
    int f4 = t & 15;
    if (e < E) {
        int s = src[e], d = dst[e];
        float nrm = dinv[s] * dinv[d];
        float4 v = *(const float4*)(xw + (size_t)s * 64 + f4 * 4);
        float* o = acc + (size_t)d * 64 + f4 * 4;
        atomicAdd(o + 0, v.x * nrm);
        atomicAdd(o + 1, v.y * nrm);
        atomicAdd(o + 2, v.z * nrm);
        atomicAdd(o + 3, v.w * nrm);
    }
}

// ---------------------------------------------------------------------------
// pooling: pool[g][colbase+f] += relu(acc[n][f] + b[f]) over nodes of graph g.
// batch is sorted; each thread keeps a register run-sum, flushing on graph
// change. 256 threads = 64 feature lanes x 4 node groups; block = 256 nodes.
// ---------------------------------------------------------------------------
#define POOL_CH 256
__global__ __launch_bounds__(256) void k_pool(const float* __restrict__ acc,
                                              const int* __restrict__ batch,
                                              const float* __restrict__ bias,
                                              int n, int colbase, int cntbase) {
    int f = threadIdx.x & 63;
    int grp = threadIdx.x >> 6;
    int n0 = blockIdx.x * POOL_CH;
    int nend = min(n0 + POOL_CH, n);
    float b = bias[f];
    float sum = 0.0f, cnt = 0.0f;
    int curg = -1;
    for (int nn = n0 + grp; nn < nend; nn += 4) {
        int g = batch[nn];
        if (g != curg) {
            if (curg >= 0) {
                atomicAdd(&g_pool[curg * 128 + colbase + f], sum);
                if (f == 0) atomicAdd(&g_cnt[cntbase + curg], cnt);
            }
            curg = g; sum = 0.0f; cnt = 0.0f;
        }
        float v = acc[(size_t)nn * 64 + f] + b;
        sum += fmaxf(v, 0.0f);
        cnt += 1.0f;
    }
    if (curg >= 0) {
        atomicAdd(&g_pool[curg * 128 + colbase + f], sum);
        if (f == 0) atomicAdd(&g_cnt[cntbase + curg], cnt);
    }
}

// ---------------------------------------------------------------------------
// final: out[g][c] = sum_j (pool[g][j]/cnt) * lin_W[j][c] + lin_b[c]
// 1 block, 256 threads (128 graphs x 2 outputs)
// ---------------------------------------------------------------------------
__global__ void k_final(const float* __restrict__ linW, const float* __restrict__ linb,
                        float* __restrict__ out) {
    int t = threadIdx.x;
    int g = t >> 1, c = t & 1;
    float cp = fmaxf(g_cnt[g], 1.0f);
    float cr = fmaxf(g_cnt[NG + g], 1.0f);
    float s = linb[c];
#pragma unroll 8
    for (int j = 0; j < 64; j++)  s += (g_pool[g * 128 + j] / cp) * linW[j * 2 + c];
#pragma unroll 8
    for (int j = 64; j < 128; j++) s += (g_pool[g * 128 + j] / cr) * linW[j * 2 + c];
    out[g * 2 + c] = s;
}

// ---------------------------------------------------------------------------
extern "C" void kernel_launch(void* const* d_in, const int* in_sizes, int n_in,
                              void* d_out, int out_size) {
    const float* p_x   = (const float*)d_in[0];
    const int*   p_ei  = (const int*)d_in[1];
    const int*   p_bat = (const int*)d_in[2];
    const float* r_x   = (const float*)d_in[3];
    const int*   r_ei  = (const int*)d_in[4];
    const int*   r_bat = (const int*)d_in[5];
    const float* p_W   = (const float*)d_in[6];
    const float* p_b   = (const float*)d_in[7];
    const float* r_W   = (const float*)d_in[8];
    const float* r_b   = (const float*)d_in[9];
    const float* linW  = (const float*)d_in[10];
    const float* linb  = (const float*)d_in[11];
    float* out = (float*)d_out;

    int Np = in_sizes[2];
    int Kp = in_sizes[0] / Np;
    int Ep = in_sizes[1] / 2;
    int Nr = in_sizes[5];
    int Kr = in_sizes[3] / Nr;
    int Er = in_sizes[4] / 2;

    float *p_xw, *r_xw, *p_acc, *r_acc, *p_dinv, *r_dinv;
    cudaGetSymbolAddress((void**)&p_xw, g_p_xw);
    cudaGetSymbolAddress((void**)&r_xw, g_r_xw);
    cudaGetSymbolAddress((void**)&p_acc, g_p_acc);
    cudaGetSymbolAddress((void**)&r_acc, g_r_acc);
    cudaGetSymbolAddress((void**)&p_dinv, g_p_dinv);
    cudaGetSymbolAddress((void**)&r_dinv, g_r_dinv);

    int nmax = (Np > Nr ? Np : Nr);
    if (nmax < NG * 128) nmax = NG * 128;

    // degrees (with self loop) and dinv
    k_init<<<(nmax + 255) / 256, 256>>>(Np, Nr);
    k_count<<<(Ep + 255) / 256, 256>>>(p_ei + Ep, Ep, p_dinv);
    k_count<<<(Er + 255) / 256, 256>>>(r_ei + Er, Er, r_dinv);
    k_dinv<<<(Np + 255) / 256, 256>>>(p_dinv, Np);
    k_dinv<<<(Nr + 255) / 256, 256>>>(r_dinv, Nr);

    // xw = x @ W
    k_gemm<<<Np / 64, 256>>>(p_x, p_W, p_xw, Np, Kp);
    k_gemm<<<Nr / 64, 256>>>(r_x, r_W, r_xw, Nr, Kr);

    // self-loop init + edge scatter
    k_selfloop<<<(Np * 16 + 255) / 256, 256>>>(p_xw, p_dinv, p_acc, Np);
    k_selfloop<<<(Nr * 16 + 255) / 256, 256>>>(r_xw, r_dinv, r_acc, Nr);
    {
        long long tp = (long long)Ep * 16;
        k_scatter<<<(unsigned)((tp + 255) / 256), 256>>>(p_ei, p_ei + Ep, p_dinv, p_xw, p_acc, Ep);
        long long tr = (long long)Er * 16;
        k_scatter<<<(unsigned)((tr + 255) / 256), 256>>>(r_ei, r_ei + Er, r_dinv, r_xw, r_acc, Er);
    }

    // bias + relu + mean pool
    k_pool<<<(Np + POOL_CH - 1) / POOL_CH, 256>>>(p_acc, p_bat, p_b, Np, 0, 0);
    k_pool<<<(Nr + POOL_CH - 1) / POOL_CH, 256>>>(r_acc, r_bat, r_b, Nr, 64, NG);

    // final linear
    k_final<<<1, 256>>>(linW, linb, out);
}

// round 3
// speedup vs baseline: 1.7041x; 1.7041x over previous
#include <cuda_runtime.h>
#include <cuda_bf16.h>
#include <cstdint>

#define NG 128
#define NPMAX 200000
#define NRMAX 400000

// ---- static scratch ----
__device__ __align__(16) float g_p_xw [NPMAX * 64];
__device__ __align__(16) float g_r_xw [NRMAX * 64];
__device__ __align__(16) float g_p_acc[NPMAX * 64];
__device__ __align__(16) float g_r_acc[NRMAX * 64];
__device__ float g_p_dinv[NPMAX];
__device__ float g_r_dinv[NRMAX];
__device__ float g_pool[NG * 128];
__device__ float g_cnt[2 * NG];
__device__ __align__(16) __nv_bfloat16 g_pWhi[64 * 1280];
__device__ __align__(16) __nv_bfloat16 g_pWlo[64 * 1280];
__device__ __align__(16) __nv_bfloat16 g_rWhi[64 * 128];
__device__ __align__(16) __nv_bfloat16 g_rWlo[64 * 128];

__device__ __forceinline__ uint32_t smem_u32(const void* p) {
    uint32_t a;
    asm("{ .reg .u64 t; cvta.to.shared.u64 t, %1; cvt.u32.u64 %0, t; }" : "=r"(a) : "l"(p));
    return a;
}

__device__ __forceinline__ void ldm_x4(uint32_t* r, uint32_t addr) {
    asm volatile("ldmatrix.sync.aligned.m8n8.x4.shared.b16 {%0,%1,%2,%3}, [%4];"
                 : "=r"(r[0]), "=r"(r[1]), "=r"(r[2]), "=r"(r[3]) : "r"(addr));
}

__device__ __forceinline__ void mma_bf16(float* d, const uint32_t* a, const uint32_t* b) {
    asm volatile(
        "mma.sync.aligned.m16n8k16.row.col.f32.bf16.bf16.f32 "
        "{%0,%1,%2,%3}, {%4,%5,%6,%7}, {%8,%9}, {%0,%1,%2,%3};"
        : "+f"(d[0]), "+f"(d[1]), "+f"(d[2]), "+f"(d[3])
        : "r"(a[0]), "r"(a[1]), "r"(a[2]), "r"(a[3]), "r"(b[0]), "r"(b[1]));
}

// ---------------------------------------------------------------------------
__global__ void k_init(int np, int nr) {
    int i = blockIdx.x * blockDim.x + threadIdx.x;
    if (i < np) g_p_dinv[i] = 1.0f;
    if (i < nr) g_r_dinv[i] = 1.0f;
    if (i < NG * 128) g_pool[i] = 0.0f;
    if (i < 2 * NG) g_cnt[i] = 0.0f;
}

__global__ void k_count(const int* __restrict__ dst, int E, float* __restrict__ deg) {
    int e = blockIdx.x * blockDim.x + threadIdx.x;
    if (e < E) atomicAdd(&deg[dst[e]], 1.0f);
}

__global__ void k_dinv(float* __restrict__ d, int n) {
    int i = blockIdx.x * blockDim.x + threadIdx.x;
    if (i < n) d[i] = rsqrtf(d[i]);
}

// W [K,64] fp32 -> Whi/Wlo [64,Kpad] bf16 (zero padded), hi/lo split
__global__ void k_prepw(const float* __restrict__ W, __nv_bfloat16* __restrict__ Whi,
                        __nv_bfloat16* __restrict__ Wlo, int K, int Kpad) {
    int i = blockIdx.x * blockDim.x + threadIdx.x;
    if (i < 64 * Kpad) {
        int n = i / Kpad, k = i % Kpad;
        float v = (k < K) ? W[k * 64 + n] : 0.0f;
        __nv_bfloat16 h = __float2bfloat16_rn(v);
        Whi[i] = h;
        Wlo[i] = __float2bfloat16_rn(v - __bfloat162float(h));
    }
}

// ---------------------------------------------------------------------------
// HMMA GEMM: XW[M,64] = X[M,K] @ W[K,64], bf16x3 (A hi/lo, W hi/lo, 3 products)
// CTA: 128 rows x 64 cols, 256 threads (8 warps; warp w -> rows w*16..w*16+15)
// K chunks of 64, staged in dynamic smem with 8-elem row padding.
// Epilogue writes xw and acc = xw * dinv^2 (self-loop term).
// ---------------------------------------------------------------------------
#define KC 64
#define APAD 8
#define ASTR (KC + APAD)            // 72 bf16 per row, 144 bytes
#define SZ_A (128 * ASTR)           // elems
#define SZ_B (64 * ASTR)
extern __shared__ __align__(16) __nv_bfloat16 dynsm[];

__global__ __launch_bounds__(256) void k_gemm_mma(
    const float* __restrict__ X,
    const __nv_bfloat16* __restrict__ Whi, const __nv_bfloat16* __restrict__ Wlo,
    const float* __restrict__ dinv,
    float* __restrict__ XW, float* __restrict__ ACC,
    int M, int K, int Kpad)
{
    __nv_bfloat16* sAhi = dynsm;
    __nv_bfloat16* sAlo = dynsm + SZ_A;
    __nv_bfloat16* sBhi = dynsm + 2 * SZ_A;
    __nv_bfloat16* sBlo = dynsm + 2 * SZ_A + SZ_B;
    uint32_t uAhi = smem_u32(sAhi), uAlo = smem_u32(sAlo);

    int tid = threadIdx.x;
    int w = tid >> 5, lane = tid & 31;
    int g = lane >> 2, tg = lane & 3;

    // A loader mapping: thread t -> row t/2, k-half (t&1)*32
    int arow = tid >> 1;
    int akh  = (tid & 1) * 32;
    int grow = blockIdx.x * 128 + arow;
    bool aOK = grow < M;
    const float* xrow = X + (size_t)grow * K;

    // B loader mapping: t<128 -> hi, t>=128 -> lo; n = (t&127)/2, k-half
    int bt = tid & 127;
    int bn = bt >> 1;
    int bkh = (bt & 1) * 32;
    const __nv_bfloat16* bsrc = ((tid < 128) ? Whi : Wlo) + (size_t)bn * Kpad + bkh;
    __nv_bfloat16* bdst = ((tid < 128) ? sBhi : sBlo) + bn * ASTR + bkh;

    // ldmatrix per-lane address offset (within A tile)
    int lrow = w * 16 + (lane & 7) + ((lane >> 3) & 1) * 8;
    int lcol = (lane >> 4) * 8;
    uint32_t aoff = (uint32_t)(lrow * ASTR + lcol) * 2;

    // B fragment per-lane byte offset (within B tile, nt=0, ks=0)
    uint32_t boff = (uint32_t)(g * ASTR + 2 * tg) * 2;

    float d[8][4];
#pragma unroll
    for (int i = 0; i < 8; i++)
#pragma unroll
        for (int j = 0; j < 4; j++) d[i][j] = 0.0f;

    int nchunks = Kpad / KC;
    for (int ch = 0; ch < nchunks; ch++) {
        int k0 = ch * KC;
        if (ch > 0) __syncthreads();  // smem free to overwrite

        // ---- stage A (fp32 -> hi/lo bf16) ----
        {
            uint32_t hi[16], lo[16];
#pragma unroll
            for (int j = 0; j < 8; j++) {
                int k = k0 + akh + j * 4;
                float4 t = (aOK && (k + 4 <= K)) ? *(const float4*)(xrow + k)
                                                 : make_float4(0.f, 0.f, 0.f, 0.f);
                float v0 = t.x, v1 = t.y, v2 = t.z, v3 = t.w;
                __nv_bfloat16 h0 = __float2bfloat16_rn(v0), h1 = __float2bfloat16_rn(v1);
                __nv_bfloat16 h2 = __float2bfloat16_rn(v2), h3 = __float2bfloat16_rn(v3);
                __nv_bfloat162 p01 = __halves2bfloat162(h0, h1);
                __nv_bfloat162 p23 = __halves2bfloat162(h2, h3);
                hi[2 * j]     = *(uint32_t*)&p01;
                hi[2 * j + 1] = *(uint32_t*)&p23;
                __nv_bfloat162 l01 = __halves2bfloat162(
                    __float2bfloat16_rn(v0 - __bfloat162float(h0)),
                    __float2bfloat16_rn(v1 - __bfloat162float(h1)));
                __nv_bfloat162 l23 = __halves2bfloat162(
                    __float2bfloat16_rn(v2 - __bfloat162float(h2)),
                    __float2bfloat16_rn(v3 - __bfloat162float(h3)));
                lo[2 * j]     = *(uint32_t*)&l01;
                lo[2 * j + 1] = *(uint32_t*)&l23;
            }
            uint32_t off = (uint32_t)(arow * ASTR + akh);
            uint4* dh = (uint4*)(sAhi + off);
            uint4* dl = (uint4*)(sAlo + off);
#pragma unroll
            for (int q = 0; q < 4; q++) {
                dh[q] = make_uint4(hi[4 * q], hi[4 * q + 1], hi[4 * q + 2], hi[4 * q + 3]);
                dl[q] = make_uint4(lo[4 * q], lo[4 * q + 1], lo[4 * q + 2], lo[4 * q + 3]);
            }
        }
        // ---- stage B (bf16 copy) ----
        {
            const uint4* s = (const uint4*)(bsrc + k0);
            uint4* dq = (uint4*)bdst;
#pragma unroll
            for (int q = 0; q < 4; q++) dq[q] = s[q];
        }
        __syncthreads();

        // ---- MMA ----
#pragma unroll
        for (int ks = 0; ks < KC / 16; ks++) {
            uint32_t ah[4], al[4];
            ldm_x4(ah, uAhi + aoff + ks * 32);
            ldm_x4(al, uAlo + aoff + ks * 32);
            const char* bhP = (const char*)sBhi + boff + ks * 32;
            const char* blP = (const char*)sBlo + boff + ks * 32;
#pragma unroll
            for (int nt = 0; nt < 8; nt++) {
                uint32_t bh[2], bl[2];
                bh[0] = *(const uint32_t*)(bhP + nt * (8 * ASTR * 2));
                bh[1] = *(const uint32_t*)(bhP + nt * (8 * ASTR * 2) + 16);
                bl[0] = *(const uint32_t*)(blP + nt * (8 * ASTR * 2));
                bl[1] = *(const uint32_t*)(blP + nt * (8 * ASTR * 2) + 16);
                mma_bf16(d[nt], ah, bh);
                mma_bf16(d[nt], al, bh);
                mma_bf16(d[nt], ah, bl);
            }
        }
    }

    // ---- epilogue: write xw and acc = xw*dinv^2 ----
#pragma unroll
    for (int rs = 0; rs < 2; rs++) {
        int row = blockIdx.x * 128 + w * 16 + g + rs * 8;
        if (row < M) {
            float dv = dinv[row];
            float sl = dv * dv;
            float* xw = XW + (size_t)row * 64;
            float* ac = ACC + (size_t)row * 64;
#pragma unroll
            for (int nt = 0; nt < 8; nt++) {
                int col = nt * 8 + 2 * tg;
                float2 v = make_float2(d[nt][2 * rs], d[nt][2 * rs + 1]);
                *(float2*)(xw + col) = v;
                *(float2*)(ac + col) = make_float2(v.x * sl, v.y * sl);
            }
        }
    }
}

// ---------------------------------------------------------------------------
// edge scatter: acc[dst] += dinv[src]*dinv[dst]*xw[src]; 16 thr/edge, v4 red
// ---------------------------------------------------------------------------
__global__ void k_scatter(const int* __restrict__ src, const int* __restrict__ dst,
                          const float* __restrict__ dinv, const float* __restrict__ xw,
                          float* __restrict__ acc, int E) {
    int t = blockIdx.x * blockDim.x + threadIdx.x;
    int e = t >> 4;
    int f4 = t & 15;
    if (e < E) {
        int s = src[e], d = dst[e];
        float nrm = dinv[s] * dinv[d];
        float4 v = *(const float4*)(xw + (size_t)s * 64 + f4 * 4);
        float* o = acc + (size_t)d * 64 + f4 * 4;
        asm volatile("red.global.add.v4.f32 [%0], {%1,%2,%3,%4};"
                     :: "l"(o), "f"(v.x * nrm), "f"(v.y * nrm), "f"(v.z * nrm), "f"(v.w * nrm)
                     : "memory");
    }
}

// ---------------------------------------------------------------------------
#define POOL_CH 256
__global__ __launch_bounds__(256) void k_pool(const float* __restrict__ acc,
                                              const int* __restrict__ batch,
                                              const float* __restrict__ bias,
                                              int n, int colbase, int cntbase) {
    int f = threadIdx.x & 63;
    int grp = threadIdx.x >> 6;
    int n0 = blockIdx.x * POOL_CH;
    int nend = min(n0 + POOL_CH, n);
    float b = bias[f];
    float sum = 0.0f, cnt = 0.0f;
    int curg = -1;
    for (int nn = n0 + grp; nn < nend; nn += 4) {
        int g = batch[nn];
        if (g != curg) {
            if (curg >= 0) {
                atomicAdd(&g_pool[curg * 128 + colbase + f], sum);
                if (f == 0) atomicAdd(&g_cnt[cntbase + curg], cnt);
            }
            curg = g; sum = 0.0f; cnt = 0.0f;
        }
        float v = acc[(size_t)nn * 64 + f] + b;
        sum += fmaxf(v, 0.0f);
        cnt += 1.0f;
    }
    if (curg >= 0) {
        atomicAdd(&g_pool[curg * 128 + colbase + f], sum);
        if (f == 0) atomicAdd(&g_cnt[cntbase + curg], cnt);
    }
}

__global__ void k_final(const float* __restrict__ linW, const float* __restrict__ linb,
                        float* __restrict__ out) {
    int t = threadIdx.x;
    int g = t >> 1, c = t & 1;
    float cp = fmaxf(g_cnt[g], 1.0f);
    float cr = fmaxf(g_cnt[NG + g], 1.0f);
    float s = linb[c];
#pragma unroll 8
    for (int j = 0; j < 64; j++)  s += (g_pool[g * 128 + j] / cp) * linW[j * 2 + c];
#pragma unroll 8
    for (int j = 64; j < 128; j++) s += (g_pool[g * 128 + j] / cr) * linW[j * 2 + c];
    out[g * 2 + c] = s;
}

// ---------------------------------------------------------------------------
extern "C" void kernel_launch(void* const* d_in, const int* in_sizes, int n_in,
                              void* d_out, int out_size) {
    const float* p_x   = (const float*)d_in[0];
    const int*   p_ei  = (const int*)d_in[1];
    const int*   p_bat = (const int*)d_in[2];
    const float* r_x   = (const float*)d_in[3];
    const int*   r_ei  = (const int*)d_in[4];
    const int*   r_bat = (const int*)d_in[5];
    const float* p_W   = (const float*)d_in[6];
    const float* p_b   = (const float*)d_in[7];
    const float* r_W   = (const float*)d_in[8];
    const float* r_b   = (const float*)d_in[9];
    const float* linW  = (const float*)d_in[10];
    const float* linb  = (const float*)d_in[11];
    float* out = (float*)d_out;

    int Np = in_sizes[2];
    int Kp = in_sizes[0] / Np;
    int Ep = in_sizes[1] / 2;
    int Nr = in_sizes[5];
    int Kr = in_sizes[3] / Nr;
    int Er = in_sizes[4] / 2;
    int KpPad = ((Kp + 63) / 64) * 64;
    int KrPad = ((Kr + 63) / 64) * 64;

    float *p_xw, *r_xw, *p_acc, *r_acc, *p_dinv, *r_dinv;
    __nv_bfloat16 *pWhi, *pWlo, *rWhi, *rWlo;
    cudaGetSymbolAddress((void**)&p_xw, g_p_xw);
    cudaGetSymbolAddress((void**)&r_xw, g_r_xw);
    cudaGetSymbolAddress((void**)&p_acc, g_p_acc);
    cudaGetSymbolAddress((void**)&r_acc, g_r_acc);
    cudaGetSymbolAddress((void**)&p_dinv, g_p_dinv);
    cudaGetSymbolAddress((void**)&r_dinv, g_r_dinv);
    cudaGetSymbolAddress((void**)&pWhi, g_pWhi);
    cudaGetSymbolAddress((void**)&pWlo, g_pWlo);
    cudaGetSymbolAddress((void**)&rWhi, g_rWhi);
    cudaGetSymbolAddress((void**)&rWlo, g_rWlo);

    static int smem_set = 0;
    int smem_bytes = (2 * SZ_A + 2 * SZ_B) * 2;  // 55296
    if (!smem_set) {
        cudaFuncSetAttribute(k_gemm_mma, cudaFuncAttributeMaxDynamicSharedMemorySize, smem_bytes);
        smem_set = 1;
    }

    int nmax = (Np > Nr ? Np : Nr);
    if (nmax < NG * 128) nmax = NG * 128;

    k_init<<<(nmax + 255) / 256, 256>>>(Np, Nr);
    k_count<<<(Ep + 255) / 256, 256>>>(p_ei + Ep, Ep, p_dinv);
    k_count<<<(Er + 255) / 256, 256>>>(r_ei + Er, Er, r_dinv);
    k_dinv<<<(Np + 255) / 256, 256>>>(p_dinv, Np);
    k_dinv<<<(Nr + 255) / 256, 256>>>(r_dinv, Nr);

    k_prepw<<<(64 * KpPad + 255) / 256, 256>>>(p_W, pWhi, pWlo, Kp, KpPad);
    k_prepw<<<(64 * KrPad + 255) / 256, 256>>>(r_W, rWhi, rWlo, Kr, KrPad);

    k_gemm_mma<<<(Np + 127) / 128, 256, smem_bytes>>>(p_x, pWhi, pWlo, p_dinv, p_xw, p_acc, Np, Kp, KpPad);
    k_gemm_mma<<<(Nr + 127) / 128, 256, smem_bytes>>>(r_x, rWhi, rWlo, r_dinv, r_xw, r_acc, Nr, Kr, KrPad);

    {
        long long tp = (long long)Ep * 16;
        k_scatter<<<(unsigned)((tp + 255) / 256), 256>>>(p_ei, p_ei + Ep, p_dinv, p_xw, p_acc, Ep);
        long long tr = (long long)Er * 16;
        k_scatter<<<(unsigned)((tr + 255) / 256), 256>>>(r_ei, r_ei + Er, r_dinv, r_xw, r_acc, Er);
    }

    k_pool<<<(Np + POOL_CH - 1) / POOL_CH, 256>>>(p_acc, p_bat, p_b, Np, 0, 0);
    k_pool<<<(Nr + POOL_CH - 1) / POOL_CH, 256>>>(r_acc, r_bat, r_b, Nr, 64, NG);

    k_final<<<1, 256>>>(linW, linb, out);
}